// round 15
// baseline (speedup 1.0000x reference)
#include <cuda_runtime.h>
#include <math.h>

// Problem constants
#define EB 4
#define BB 16
#define SB 256
#define CB 17
#define NB 16
#define DB 32
#define DFFB 64
#define HB 4
#define DHB 8

typedef unsigned long long ull;

// ---- packed fp32x2 helpers (sm_103a) ----
__device__ __forceinline__ ull pack2(float a, float b) {
    ull r; asm("mov.b64 %0, {%1, %2};" : "=l"(r) : "f"(a), "f"(b)); return r;
}
__device__ __forceinline__ void unpack2(ull v, float& a, float& b) {
    asm("mov.b64 {%0, %1}, %2;" : "=f"(a), "=f"(b) : "l"(v));
}
__device__ __forceinline__ ull ffma2(ull a, ull b, ull c) {
    ull d; asm("fma.rn.f32x2 %0, %1, %2, %3;" : "=l"(d) : "l"(a), "l"(b), "l"(c)); return d;
}
__device__ __forceinline__ ull fmul2(ull a, ull b) {
    ull d; asm("mul.rn.f32x2 %0, %1, %2;" : "=l"(d) : "l"(a), "l"(b)); return d;
}
__device__ __forceinline__ ull fadd2(ull a, ull b) {
    ull d; asm("add.rn.f32x2 %0, %1, %2;" : "=l"(d) : "l"(a), "l"(b)); return d;
}

// Scratch (device globals; no allocations allowed)
__device__ float g_xns[BB * SB * NB];   // new_x channels 0..15
__device__ int   g_glist[BB * SB];      // per-b compacted s-indices, sorted by (expert, s)
__device__ int   g_off[BB * EB];        // per-b start offset of expert e
__device__ int   g_ecnt[BB * EB];       // per-b count of expert e

// ---------------------------------------------------------------------------
// Kernel 1: decomposition preprocessing. One block per (b, c), c<16.
// 512 threads: 4 threads per DFT frequency (64-iteration chains).
// ---------------------------------------------------------------------------
__global__ void preprocess_kernel(const float* __restrict__ x)
{
    __shared__ float xr[SB];
    __shared__ float ctab[SB], stab[SB];
    __shared__ float Xre[129], Xim[129], amp[129];
    __shared__ int   s_kept[128];
    __shared__ int   s_keptN;

    const int c = blockIdx.x;
    const int b = blockIdx.y;
    const int t = threadIdx.x;   // 0..511

    if (t < 256) {
        xr[t] = x[(b * SB + t) * CB + c];
        const float W2PI = 6.283185307179586f / 256.f;
        float sn, cs;
        sincosf(t * W2PI, &sn, &cs);
        ctab[t] = cs; stab[t] = sn;
    }
    __syncthreads();

    // ---- rDFT: thread (f, qtr) sums u in [qtr*64, qtr*64+64) ----
    {
        const int f   = t >> 2;     // 0..127
        const int qtr = t & 3;
        const int u0  = qtr * 64;
        float re = 0.f, im = 0.f;
        float ssum = 0.f, asum = 0.f;
        #pragma unroll 4
        for (int uu = 0; uu < 64; uu++) {
            const int u = u0 + uu;
            const float xv = xr[u];
            const int ph = (f * u) & 255;
            re = fmaf(xv,  ctab[ph], re);
            im = fmaf(xv, -stab[ph], im);
            ssum += xv;
            asum += (u & 1) ? -xv : xv;
        }
        re   += __shfl_xor_sync(0xffffffffu, re, 1);
        im   += __shfl_xor_sync(0xffffffffu, im, 1);
        ssum += __shfl_xor_sync(0xffffffffu, ssum, 1);
        asum += __shfl_xor_sync(0xffffffffu, asum, 1);
        re   += __shfl_xor_sync(0xffffffffu, re, 2);
        im   += __shfl_xor_sync(0xffffffffu, im, 2);
        ssum += __shfl_xor_sync(0xffffffffu, ssum, 2);
        asum += __shfl_xor_sync(0xffffffffu, asum, 2);
        if (qtr == 0) {
            if (f == 0) {
                Xre[0] = ssum; Xim[0] = 0.f; amp[0] = 0.f;   // f=0 excluded in ref
                Xre[128] = asum; Xim[128] = 0.f; amp[128] = fabsf(asum);
            } else {
                Xre[f] = re; Xim[f] = im;
                amp[f] = sqrtf(re * re + im * im);
            }
        }
    }
    __syncthreads();

    // ---- top-4 threshold among f=1..128 ----
    if (t == 0) {
        float b0 = -1e30f, b1v = -1e30f, b2v = -1e30f, b3v = -1e30f;
        for (int f = 1; f <= 128; f++) {
            float a = amp[f];
            if (a > b3v) {
                if (a > b0)       { b3v = b2v; b2v = b1v; b1v = b0; b0 = a; }
                else if (a > b1v) { b3v = b2v; b2v = b1v; b1v = a; }
                else if (a > b2v) { b3v = b2v; b2v = a; }
                else              { b3v = a; }
            }
        }
        int cnt = 0;
        for (int f = 1; f <= 128; f++)
            if (amp[f] >= b3v) s_kept[cnt++] = f;
        s_keptN = cnt;
    }
    __syncthreads();

    if (t < 256) {
        // ---- trend: mean of moving averages with kernels 4, 8, 12 ----
        float tr = 0.f;
        #pragma unroll
        for (int ki = 0; ki < 3; ki++) {
            const int k = (ki == 0) ? 4 : (ki == 1 ? 8 : 12);
            const int pf = (k - 1) >> 1;
            float a = 0.f;
            for (int j = 0; j < k; j++) {
                int idx = t + j - pf;
                idx = idx < 0 ? 0 : (idx > SB - 1 ? SB - 1 : idx);
                a += xr[idx];
            }
            tr += a / (float)k;
        }
        tr *= (1.f / 3.f);

        // ---- inverse transform of masked spectrum ----
        float season = 0.f;
        const int kn = s_keptN;
        for (int ii = 0; ii < kn; ii++) {
            int f = s_kept[ii];
            int ph = (f * t) & 255;
            if (f == 128) {
                season += Xre[128] * ctab[ph];
            } else {
                season += 2.f * (Xre[f] * ctab[ph] - Xim[f] * stab[ph]);
            }
        }
        season *= (1.f / 256.f);

        g_xns[(b * SB + t) * NB + c] = xr[t] + season + tr;
    }
}

// ---------------------------------------------------------------------------
// Kernel 2: min/max -> bins -> assignment -> per-b expert-sorted lists.
// ---------------------------------------------------------------------------
__global__ void assign_kernel(const float* __restrict__ orig)
{
    __shared__ float smn[256], smx[256];
    __shared__ float bins[EB + 1];
    __shared__ int   sA[BB * SB];
    const int t = threadIdx.x;

    float mn = 1e30f, mx = -1e30f;
    for (int i = t; i < BB * SB; i += 256) {
        float v = orig[2 * i + 1];
        mn = fminf(mn, v);
        mx = fmaxf(mx, v);
    }
    smn[t] = mn; smx[t] = mx;
    __syncthreads();
    for (int off = 128; off > 0; off >>= 1) {
        if (t < off) {
            smn[t] = fminf(smn[t], smn[t + off]);
            smx[t] = fmaxf(smx[t], smx[t + off]);
        }
        __syncthreads();
    }
    if (t == 0) {
        float lo = smn[0], hi = smx[0];
        float st = (hi - lo) * 0.25f;
        for (int j = 0; j <= EB; j++) bins[j] = lo + j * st;
    }
    __syncthreads();
    for (int i = t; i < BB * SB; i += 256) {
        float v = orig[2 * i + 1];
        int cnt = 0;
        #pragma unroll
        for (int j = 0; j <= EB; j++) cnt += (bins[j] <= v) ? 1 : 0;
        int a = cnt - 1;
        a = a < 0 ? 0 : (a > EB - 1 ? EB - 1 : a);
        sA[i] = a;
    }
    __syncthreads();

    if (t < BB) {
        const int base = t * SB;
        int cnt[EB] = {0, 0, 0, 0};
        for (int s = 0; s < SB; s++) cnt[sA[base + s]]++;
        int off[EB];
        off[0] = 0;
        #pragma unroll
        for (int e = 1; e < EB; e++) off[e] = off[e - 1] + cnt[e - 1];
        #pragma unroll
        for (int e = 0; e < EB; e++) {
            g_off[t * EB + e]  = off[e];
            g_ecnt[t * EB + e] = cnt[e];
        }
        int pos[EB];
        #pragma unroll
        for (int e = 0; e < EB; e++) pos[e] = off[e];
        for (int s = 0; s < SB; s++) {
            int a = sA[base + s];
            g_glist[base + pos[a]] = s;
            pos[a]++;
        }
    }
}

// ---------------------------------------------------------------------------
// Packed 32x32 matvec: Wsm row-major [k][j], vin scalar[32], acc = 16 pairs.
// ---------------------------------------------------------------------------
__device__ __forceinline__ void matvec32p(const float* __restrict__ Wsm,
                                          const float (&vin)[32],
                                          ull (&acc)[16])
{
    #pragma unroll
    for (int k2 = 0; k2 < 32; k2++) {
        const ull zz = pack2(vin[k2], vin[k2]);
        const ulonglong2* wr = reinterpret_cast<const ulonglong2*>(Wsm + k2 * 32);
        #pragma unroll
        for (int j = 0; j < 8; j++) {
            const ulonglong2 w = wr[j];
            acc[2*j]     = ffma2(zz, w.x, acc[2*j]);
            acc[2*j + 1] = ffma2(zz, w.y, acc[2*j + 1]);
        }
    }
}

// ---------------------------------------------------------------------------
// Kernel 3: merged 4-expert forward, 2 threads per query (pair = t&1 owns
// heads {2*pair, 2*pair+1}). 512 threads per (n,b) block -> 4 warps/SMSP.
// Even lane computes the K row, odd lane the V row (pointer select, no
// divergence). Partial h2/h3 combined across the pair via shfl_xor + f32x2 add.
// ---------------------------------------------------------------------------
#define WSTR   8192
#define KV_STRIDE 36
#define OFF_LN1G 32768
#define OFF_LN1B 32896
#define OFF_LN2G 33024
#define OFF_LN2B 33152
#define OFF_B1   33280
#define OFF_B2   33536
#define OFF_SSW  33664
#define OFF_SSB  33696
#define OFF_KC   33728
#define OFF_VC   33856
#define OFF_INTS 33984
#define OFF_K    34048
#define OFF_V    (34048 + SB * KV_STRIDE)
#define SMEM_FLOATS (OFF_V + SB * KV_STRIDE)

__global__ void __launch_bounds__(512, 1) expert_kernel(
    const float* __restrict__ startW, const float* __restrict__ startb,
    const float* __restrict__ Wq, const float* __restrict__ Wk,
    const float* __restrict__ Wv, const float* __restrict__ Wo,
    const float* __restrict__ ln1g, const float* __restrict__ ln1b,
    const float* __restrict__ ln2g, const float* __restrict__ ln2b,
    const float* __restrict__ W1, const float* __restrict__ b1,
    const float* __restrict__ W2, const float* __restrict__ b2,
    float* __restrict__ out)
{
    extern __shared__ float sm[];
    float* sKc = sm + OFF_KC;
    float* sVc = sm + OFF_VC;
    float* Ksm = sm + OFF_K;
    float* Vsm = sm + OFF_V;
    int*   sI  = reinterpret_cast<int*>(sm + OFF_INTS);

    const int t = threadIdx.x;        // 0..511
    const int n = blockIdx.x, b = blockIdx.y;

    // ---- stage all 4 experts' weights ----
    {
        const float4* gq = reinterpret_cast<const float4*>(Wq);
        const float4* gk = reinterpret_cast<const float4*>(Wk);
        const float4* gv = reinterpret_cast<const float4*>(Wv);
        const float4* go = reinterpret_cast<const float4*>(Wo);
        #pragma unroll
        for (int i = t; i < 1024; i += 512) {
            const int e = i >> 8, idx = i & 255;
            float4* dst = reinterpret_cast<float4*>(sm + e * WSTR);
            dst[idx]        = gq[i];
            dst[256 + idx]  = gk[i];
            dst[512 + idx]  = gv[i];
            dst[768 + idx]  = go[i];
        }
        const float4* g1 = reinterpret_cast<const float4*>(W1);
        const float4* g2 = reinterpret_cast<const float4*>(W2);
        #pragma unroll
        for (int i = t; i < 2048; i += 512) {
            const int e = i >> 9, idx = i & 511;
            float4* dst = reinterpret_cast<float4*>(sm + e * WSTR + 4096);
            dst[idx]        = g1[i];
            dst[512 + idx]  = g2[i];
        }
        if (t < 128) {
            sm[OFF_LN1G + t] = ln1g[t];
            sm[OFF_LN1B + t] = ln1b[t];
            sm[OFF_LN2G + t] = ln2g[t];
            sm[OFF_LN2B + t] = ln2b[t];
            sm[OFF_B2 + t]   = b2[t];
        }
        if (t < 256) sm[OFF_B1 + t] = b1[t];
        if (t < 32) {
            sm[OFF_SSW + t] = startW[t];
            sm[OFF_SSB + t] = startb[t];
        }
        if (t < 4) {
            sI[t]     = g_off[b * EB + t];
            sI[4 + t] = g_ecnt[b * EB + t];
        }
    }
    __syncthreads();

    const float* ssW = sm + OFF_SSW;
    const float* ssb = sm + OFF_SSB;

    // ---- per-expert constant key/value (h_const = start_b) ----
    if (t < 128) {
        const int ce = t >> 5;
        const int d  = t & 31;
        float m = 0.f;
        #pragma unroll
        for (int dd = 0; dd < 32; dd++) m += ssb[dd];
        m *= (1.f / 32.f);
        float var = 0.f;
        #pragma unroll
        for (int dd = 0; dd < 32; dd++) { float df = ssb[dd] - m; var = fmaf(df, df, var); }
        var *= (1.f / 32.f);
        const float r = rsqrtf(var + 1e-5f);
        const float* l1g_ = sm + OFF_LN1G + ce * 32;
        const float* l1b_ = sm + OFF_LN1B + ce * 32;
        const float* wk_  = sm + ce * WSTR + 1024;
        const float* wv_  = sm + ce * WSTR + 2048;
        float kc = 0.f, vc = 0.f;
        #pragma unroll
        for (int k2 = 0; k2 < 32; k2++) {
            float zc = fmaf((ssb[k2] - m) * r, l1g_[k2], l1b_[k2]);
            kc = fmaf(zc, wk_[k2 * 32 + d], kc);
            vc = fmaf(zc, wv_[k2 * 32 + d], vc);
        }
        sKc[ce * 32 + d] = kc;
        sVc[ce * 32 + d] = vc;
    }

    // ---- this thread-pair's query ----
    const int pair = t & 1;           // 0: heads 0-1 + K row;  1: heads 2-3 + V row
    const int qi   = t >> 1;          // query slot 0..255
    const int hoff = pair * 16;       // float offset of this thread's 2 heads
    const int e = (qi >= sI[1]) + (qi >= sI[2]) + (qi >= sI[3]);
    const int s = g_glist[b * SB + qi];
    const float xval = g_xns[(b * SB + s) * NB + n];

    const float* wb   = sm + e * WSTR;
    const float* l1g_ = sm + OFF_LN1G + e * 32;
    const float* l1b_ = sm + OFF_LN1B + e * 32;
    const float* l2g_ = sm + OFF_LN2G + e * 32;
    const float* l2b_ = sm + OFF_LN2B + e * 32;
    const float* b1_  = sm + OFF_B1 + e * 64;
    const float* b2_  = sm + OFF_B2 + e * 32;

    // ---- z = LN1(xval*startW + startb)  (duplicated across the pair) ----
    float z[32];
    {
        float mean = 0.f;
        #pragma unroll
        for (int d = 0; d < 32; d++) { z[d] = fmaf(xval, ssW[d], ssb[d]); mean += z[d]; }
        mean *= (1.f / 32.f);
        float var = 0.f;
        #pragma unroll
        for (int d = 0; d < 32; d++) { float dd = z[d] - mean; var = fmaf(dd, dd, var); }
        var *= (1.f / 32.f);
        float r = rsqrtf(var + 1e-5f);
        #pragma unroll
        for (int d = 0; d < 32; d++)
            z[d] = fmaf((z[d] - mean) * r, l1g_[d], l1b_[d]);
    }

    // ---- q slice (16 floats = 8 packed), scale folded in ----
    const float att_scale = 0.3535533905932738f; // 1/sqrt(8)
    ull q2[8];
    {
        #pragma unroll
        for (int i = 0; i < 8; i++) q2[i] = 0ull;
        #pragma unroll
        for (int k2 = 0; k2 < 32; k2++) {
            const ull zz = pack2(z[k2], z[k2]);
            const ulonglong2* wr = reinterpret_cast<const ulonglong2*>(wb + k2 * 32 + hoff);
            const ulonglong2 w0 = wr[0], w1 = wr[1];
            q2[0] = ffma2(zz, w0.x, q2[0]); q2[1] = ffma2(zz, w0.y, q2[1]);
            q2[2] = ffma2(zz, w1.x, q2[2]); q2[3] = ffma2(zz, w1.y, q2[3]);
            const ulonglong2 w2 = wr[2], w3 = wr[3];
            q2[4] = ffma2(zz, w2.x, q2[4]); q2[5] = ffma2(zz, w2.y, q2[5]);
            q2[6] = ffma2(zz, w3.x, q2[6]); q2[7] = ffma2(zz, w3.y, q2[7]);
        }
        const ull sc2 = pack2(att_scale, att_scale);
        #pragma unroll
        for (int i = 0; i < 8; i++) q2[i] = fmul2(q2[i], sc2);
    }

    // ---- K row (even lane) or V row (odd lane): pointer select, no branch ----
    {
        const float* wkv = wb + (pair ? 2048 : 1024);
        float* dstrow = (pair ? Vsm : Ksm) + qi * KV_STRIDE;
        ull acc[16];
        #pragma unroll
        for (int i = 0; i < 16; i++) acc[i] = 0ull;
        matvec32p(wkv, z, acc);
        ulonglong2* dw = reinterpret_cast<ulonglong2*>(dstrow);
        #pragma unroll
        for (int j = 0; j < 8; j++) {
            ulonglong2 v; v.x = acc[2*j]; v.y = acc[2*j+1];
            dw[j] = v;
        }
    }
    __syncthreads();

    // ---- attention over this expert's keys + aggregated const key ----
    const int koff = sI[e];
    const int kend = koff + sI[4 + e];

    ull o2[8];
    #pragma unroll
    for (int i = 0; i < 8; i++) o2[i] = 0ull;
    float lsum[2] = {0.f, 0.f};

    #pragma unroll 2
    for (int key = koff; key < kend; key++) {
        const ulonglong2* kr = reinterpret_cast<const ulonglong2*>(Ksm + key * KV_STRIDE + hoff);
        const ulonglong2* vr = reinterpret_cast<const ulonglong2*>(Vsm + key * KV_STRIDE + hoff);
        #pragma unroll
        for (int hh = 0; hh < 2; hh++) {
            const ulonglong2 k01 = kr[2*hh], k23 = kr[2*hh + 1];
            ull lg2 = fmul2(q2[4*hh], k01.x);
            lg2 = ffma2(q2[4*hh + 1], k01.y, lg2);
            lg2 = ffma2(q2[4*hh + 2], k23.x, lg2);
            lg2 = ffma2(q2[4*hh + 3], k23.y, lg2);
            float lo, hi;
            unpack2(lg2, lo, hi);
            const float p = __expf(fminf(lo + hi, 80.f));
            lsum[hh] += p;
            const ull pp = pack2(p, p);
            const ulonglong2 v01 = vr[2*hh], v23 = vr[2*hh + 1];
            o2[4*hh]     = ffma2(pp, v01.x, o2[4*hh]);
            o2[4*hh + 1] = ffma2(pp, v01.y, o2[4*hh + 1]);
            o2[4*hh + 2] = ffma2(pp, v23.x, o2[4*hh + 2]);
            o2[4*hh + 3] = ffma2(pp, v23.y, o2[4*hh + 3]);
        }
    }
    {
        const float w = (float)(SB - sI[4 + e]);
        const ulonglong2* kr = reinterpret_cast<const ulonglong2*>(sKc + e * 32 + hoff);
        const ulonglong2* vr = reinterpret_cast<const ulonglong2*>(sVc + e * 32 + hoff);
        #pragma unroll
        for (int hh = 0; hh < 2; hh++) {
            const ulonglong2 k01 = kr[2*hh], k23 = kr[2*hh + 1];
            ull lg2 = fmul2(q2[4*hh], k01.x);
            lg2 = ffma2(q2[4*hh + 1], k01.y, lg2);
            lg2 = ffma2(q2[4*hh + 2], k23.x, lg2);
            lg2 = ffma2(q2[4*hh + 3], k23.y, lg2);
            float lo, hi;
            unpack2(lg2, lo, hi);
            const float p = w * __expf(fminf(lo + hi, 80.f));
            lsum[hh] += p;
            const ull pp = pack2(p, p);
            const ulonglong2 v01 = vr[2*hh], v23 = vr[2*hh + 1];
            o2[4*hh]     = ffma2(pp, v01.x, o2[4*hh]);
            o2[4*hh + 1] = ffma2(pp, v01.y, o2[4*hh + 1]);
            o2[4*hh + 2] = ffma2(pp, v23.x, o2[4*hh + 2]);
            o2[4*hh + 3] = ffma2(pp, v23.y, o2[4*hh + 3]);
        }
    }

    // normalize this thread's 16 o values
    float o[16];
    #pragma unroll
    for (int hh = 0; hh < 2; hh++) {
        const float inv = 1.0f / lsum[hh];
        #pragma unroll
        for (int j = 0; j < 4; j++) {
            float a, c;
            unpack2(o2[4*hh + j], a, c);
            o[8*hh + 2*j]     = a * inv;
            o[8*hh + 2*j + 1] = c * inv;
        }
    }

    // ---- h2 = h + o @ Wo : partial over this thread's 16 Wo rows, pair-combined
    float h2[32];
    {
        ull acc[16];
        #pragma unroll
        for (int j = 0; j < 16; j++) {
            const float r0 = pair ? 0.f : fmaf(xval, ssW[2*j],     ssb[2*j]);
            const float r1 = pair ? 0.f : fmaf(xval, ssW[2*j + 1], ssb[2*j + 1]);
            acc[j] = pack2(r0, r1);
        }
        const float* wo = wb + 3072 + hoff * 32;
        #pragma unroll
        for (int r = 0; r < 16; r++) {
            const ull fj = pack2(o[r], o[r]);
            const ulonglong2* wr = reinterpret_cast<const ulonglong2*>(wo + r * 32);
            #pragma unroll
            for (int j = 0; j < 8; j++) {
                const ulonglong2 w = wr[j];
                acc[2*j]     = ffma2(fj, w.x, acc[2*j]);
                acc[2*j + 1] = ffma2(fj, w.y, acc[2*j + 1]);
            }
        }
        #pragma unroll
        for (int j = 0; j < 16; j++) {
            const ull other = __shfl_xor_sync(0xffffffffu, acc[j], 1);
            acc[j] = fadd2(acc[j], other);              // commutative -> identical in both lanes
            unpack2(acc[j], h2[2*j], h2[2*j + 1]);
        }
    }

    // ---- z2 = LN2(h2)  (identical in both lanes) ----
    float z2[32];
    {
        float mean = 0.f;
        #pragma unroll
        for (int d = 0; d < 32; d++) mean += h2[d];
        mean *= (1.f / 32.f);
        float var = 0.f;
        #pragma unroll
        for (int d = 0; d < 32; d++) { float dd = h2[d] - mean; var = fmaf(dd, dd, var); }
        var *= (1.f / 32.f);
        float r = rsqrtf(var + 1e-5f);
        #pragma unroll
        for (int d = 0; d < 32; d++)
            z2[d] = fmaf((h2[d] - mean) * r, l2g_[d], l2b_[d]);
    }

    // ---- FFN: this thread's 32 of 64 f-dims; h3 partial, pair-combined ----
    const int f0 = pair * 32;
    const float* sW1 = wb + 4096;
    const float* sW2 = wb + 6144;

    ull fh2[16];
    #pragma unroll
    for (int j = 0; j < 16; j++)
        fh2[j] = pack2(b1_[f0 + 2*j], b1_[f0 + 2*j + 1]);
    #pragma unroll
    for (int k2 = 0; k2 < 32; k2++) {
        const ull zz = pack2(z2[k2], z2[k2]);
        const ulonglong2* wr = reinterpret_cast<const ulonglong2*>(sW1 + k2 * 64 + f0);
        #pragma unroll
        for (int j = 0; j < 16; j++) {
            const ulonglong2 w = wr[j >> 1];
            fh2[j] = ffma2(zz, (j & 1) ? w.y : w.x, fh2[j]);
        }
    }
    float fh[32];
    #pragma unroll
    for (int j = 0; j < 16; j++) {
        float a, c;
        unpack2(fh2[j], a, c);
        fh[2*j]     = fmaxf(a, 0.f);
        fh[2*j + 1] = fmaxf(c, 0.f);
    }

    ull h32[16];
    #pragma unroll
    for (int j = 0; j < 16; j++) {
        const float r0 = pair ? 0.f : (h2[2*j]     + b2_[2*j]);
        const float r1 = pair ? 0.f : (h2[2*j + 1] + b2_[2*j + 1]);
        h32[j] = pack2(r0, r1);
    }
    #pragma unroll
    for (int j = 0; j < 32; j++) {
        const ull fj = pack2(fh[j], fh[j]);
        const ulonglong2* wr = reinterpret_cast<const ulonglong2*>(sW2 + (f0 + j) * 32);
        #pragma unroll
        for (int d = 0; d < 16; d++) {
            const ulonglong2 w = wr[d >> 1];
            h32[d] = ffma2(fj, (d & 1) ? w.y : w.x, h32[d]);
        }
    }
    #pragma unroll
    for (int j = 0; j < 16; j++) {
        const ull other = __shfl_xor_sync(0xffffffffu, h32[j], 1);
        h32[j] = fadd2(h32[j], other);
    }

    // ---- write: even lane writes dims 0..15, odd lane dims 16..31 ----
    {
        const int bs = b * SB + s;
        ulonglong2* op = reinterpret_cast<ulonglong2*>(out + ((bs * NB) + n) * DB);
        #pragma unroll
        for (int j = 0; j < 4; j++) {
            const int jj = pair * 8 + 2 * j;
            ulonglong2 v; v.x = h32[jj]; v.y = h32[jj + 1];
            op[pair * 4 + j] = v;
        }
    }
}

// ---------------------------------------------------------------------------
extern "C" void kernel_launch(void* const* d_in, const int* in_sizes, int n_in,
                              void* d_out, int out_size)
{
    const float* x      = (const float*)d_in[0];
    const float* orig   = (const float*)d_in[1];
    const float* startW = (const float*)d_in[2];
    const float* startb = (const float*)d_in[3];
    const float* Wq     = (const float*)d_in[4];
    const float* Wk     = (const float*)d_in[5];
    const float* Wv     = (const float*)d_in[6];
    const float* Wo     = (const float*)d_in[7];
    const float* l1g    = (const float*)d_in[8];
    const float* l1b    = (const float*)d_in[9];
    const float* l2g    = (const float*)d_in[10];
    const float* l2b    = (const float*)d_in[11];
    const float* W1     = (const float*)d_in[12];
    const float* b1     = (const float*)d_in[13];
    const float* W2     = (const float*)d_in[14];
    const float* b2     = (const float*)d_in[15];
    float* out = (float*)d_out;

    preprocess_kernel<<<dim3(NB, BB), 512>>>(x);
    assign_kernel<<<1, 256>>>(orig);

    const int smem_bytes = SMEM_FLOATS * (int)sizeof(float);
    cudaFuncSetAttribute(expert_kernel,
                         cudaFuncAttributeMaxDynamicSharedMemorySize, smem_bytes);
    expert_kernel<<<dim3(NB, BB), 512, smem_bytes>>>(
        startW, startb, Wq, Wk, Wv, Wo,
        l1g, l1b, l2g, l2b, W1, b1, W2, b2, out);
}

// round 17
// speedup vs baseline: 1.2750x; 1.2750x over previous
#include <cuda_runtime.h>
#include <math.h>

// Problem constants
#define EB 4
#define BB 16
#define SB 256
#define CB 17
#define NB 16
#define DB 32
#define DFFB 64
#define HB 4
#define DHB 8

typedef unsigned long long ull;

// ---- packed fp32x2 helpers (sm_103a) ----
__device__ __forceinline__ ull pack2(float a, float b) {
    ull r; asm("mov.b64 %0, {%1, %2};" : "=l"(r) : "f"(a), "f"(b)); return r;
}
__device__ __forceinline__ void unpack2(ull v, float& a, float& b) {
    asm("mov.b64 {%0, %1}, %2;" : "=f"(a), "=f"(b) : "l"(v));
}
__device__ __forceinline__ ull ffma2(ull a, ull b, ull c) {
    ull d; asm("fma.rn.f32x2 %0, %1, %2, %3;" : "=l"(d) : "l"(a), "l"(b), "l"(c)); return d;
}
__device__ __forceinline__ ull fmul2(ull a, ull b) {
    ull d; asm("mul.rn.f32x2 %0, %1, %2;" : "=l"(d) : "l"(a), "l"(b)); return d;
}

// Scratch (device globals; no allocations allowed)
__device__ float g_xns[BB * SB * NB];   // new_x channels 0..15
__device__ int   g_glist[BB * SB];      // per-b compacted s-indices, sorted by (expert, s)
__device__ int   g_off[BB * EB];        // per-b start offset of expert e
__device__ int   g_ecnt[BB * EB];       // per-b count of expert e

// ---------------------------------------------------------------------------
// Kernel 1: decomposition preprocessing. One block per (b, c), c<16.
// (R14 256-thread version — the 512-thread split regressed.)
// ---------------------------------------------------------------------------
__global__ void preprocess_kernel(const float* __restrict__ x)
{
    __shared__ float xr[SB];
    __shared__ float ctab[SB], stab[SB];
    __shared__ float Xre[129], Xim[129], amp[129];
    __shared__ int   s_kept[128];
    __shared__ int   s_keptN;

    const int c = blockIdx.x;
    const int b = blockIdx.y;
    const int t = threadIdx.x;

    xr[t] = x[(b * SB + t) * CB + c];
    {
        const float W2PI = 6.283185307179586f / 256.f;
        float sn, cs;
        sincosf(t * W2PI, &sn, &cs);
        ctab[t] = cs; stab[t] = sn;
    }
    __syncthreads();

    // ---- trend: mean of moving averages with kernels 4, 8, 12 ----
    float tr = 0.f;
    {
        #pragma unroll
        for (int ki = 0; ki < 3; ki++) {
            const int k = (ki == 0) ? 4 : (ki == 1 ? 8 : 12);
            const int pf = (k - 1) >> 1;
            float a = 0.f;
            for (int j = 0; j < k; j++) {
                int idx = t + j - pf;
                idx = idx < 0 ? 0 : (idx > SB - 1 ? SB - 1 : idx);
                a += xr[idx];
            }
            tr += a / (float)k;
        }
        tr *= (1.f / 3.f);
    }

    // ---- rDFT: thread (f, half) sums u in [half*128, half*128+128) ----
    {
        const int f    = t >> 1;
        const int half = t & 1;
        const int u0   = half * 128;
        float re = 0.f, im = 0.f;
        float ssum = 0.f, asum = 0.f;
        #pragma unroll 4
        for (int uu = 0; uu < 128; uu++) {
            const int u = u0 + uu;
            const float xv = xr[u];
            const int ph = (f * u) & 255;
            re = fmaf(xv,  ctab[ph], re);
            im = fmaf(xv, -stab[ph], im);
            ssum += xv;
            asum += (u & 1) ? -xv : xv;
        }
        re   += __shfl_xor_sync(0xffffffffu, re, 1);
        im   += __shfl_xor_sync(0xffffffffu, im, 1);
        ssum += __shfl_xor_sync(0xffffffffu, ssum, 1);
        asum += __shfl_xor_sync(0xffffffffu, asum, 1);
        if (half == 0) {
            if (f == 0) {
                Xre[0] = ssum; Xim[0] = 0.f; amp[0] = 0.f;   // f=0 excluded in ref
                Xre[128] = asum; Xim[128] = 0.f; amp[128] = fabsf(asum);
            } else {
                Xre[f] = re; Xim[f] = im;
                amp[f] = sqrtf(re * re + im * im);
            }
        }
    }
    __syncthreads();

    // ---- top-4 threshold among f=1..128 ----
    if (t == 0) {
        float b0 = -1e30f, b1v = -1e30f, b2v = -1e30f, b3v = -1e30f;
        for (int f = 1; f <= 128; f++) {
            float a = amp[f];
            if (a > b3v) {
                if (a > b0)       { b3v = b2v; b2v = b1v; b1v = b0; b0 = a; }
                else if (a > b1v) { b3v = b2v; b2v = b1v; b1v = a; }
                else if (a > b2v) { b3v = b2v; b2v = a; }
                else              { b3v = a; }
            }
        }
        int cnt = 0;
        for (int f = 1; f <= 128; f++)
            if (amp[f] >= b3v) s_kept[cnt++] = f;
        s_keptN = cnt;
    }
    __syncthreads();

    // ---- inverse transform of masked spectrum ----
    float season = 0.f;
    const int kn = s_keptN;
    for (int ii = 0; ii < kn; ii++) {
        int f = s_kept[ii];
        int ph = (f * t) & 255;
        if (f == 128) {
            season += Xre[128] * ctab[ph];
        } else {
            season += 2.f * (Xre[f] * ctab[ph] - Xim[f] * stab[ph]);
        }
    }
    season *= (1.f / 256.f);

    g_xns[(b * SB + t) * NB + c] = xr[t] + season + tr;
}

// ---------------------------------------------------------------------------
// Kernel 2: min/max -> bins -> assignment -> per-b expert-sorted lists.
// ---------------------------------------------------------------------------
__global__ void assign_kernel(const float* __restrict__ orig)
{
    __shared__ float smn[256], smx[256];
    __shared__ float bins[EB + 1];
    __shared__ int   sA[BB * SB];
    const int t = threadIdx.x;

    float mn = 1e30f, mx = -1e30f;
    for (int i = t; i < BB * SB; i += 256) {
        float v = orig[2 * i + 1];
        mn = fminf(mn, v);
        mx = fmaxf(mx, v);
    }
    smn[t] = mn; smx[t] = mx;
    __syncthreads();
    for (int off = 128; off > 0; off >>= 1) {
        if (t < off) {
            smn[t] = fminf(smn[t], smn[t + off]);
            smx[t] = fmaxf(smx[t], smx[t + off]);
        }
        __syncthreads();
    }
    if (t == 0) {
        float lo = smn[0], hi = smx[0];
        float st = (hi - lo) * 0.25f;
        for (int j = 0; j <= EB; j++) bins[j] = lo + j * st;
    }
    __syncthreads();
    for (int i = t; i < BB * SB; i += 256) {
        float v = orig[2 * i + 1];
        int cnt = 0;
        #pragma unroll
        for (int j = 0; j <= EB; j++) cnt += (bins[j] <= v) ? 1 : 0;
        int a = cnt - 1;
        a = a < 0 ? 0 : (a > EB - 1 ? EB - 1 : a);
        sA[i] = a;
    }
    __syncthreads();

    if (t < BB) {
        const int base = t * SB;
        int cnt[EB] = {0, 0, 0, 0};
        for (int s = 0; s < SB; s++) cnt[sA[base + s]]++;
        int off[EB];
        off[0] = 0;
        #pragma unroll
        for (int e = 1; e < EB; e++) off[e] = off[e - 1] + cnt[e - 1];
        #pragma unroll
        for (int e = 0; e < EB; e++) {
            g_off[t * EB + e]  = off[e];
            g_ecnt[t * EB + e] = cnt[e];
        }
        int pos[EB];
        #pragma unroll
        for (int e = 0; e < EB; e++) pos[e] = off[e];
        for (int s = 0; s < SB; s++) {
            int a = sA[base + s];
            g_glist[base + pos[a]] = s;
            pos[a]++;
        }
    }
}

// ---------------------------------------------------------------------------
// Packed 32x32 matvec: Wsm row-major [k][j], vin scalar[32], acc = 16 pairs.
// ---------------------------------------------------------------------------
__device__ __forceinline__ void matvec32p(const float* __restrict__ Wsm,
                                          const float (&vin)[32],
                                          ull (&acc)[16])
{
    #pragma unroll
    for (int k2 = 0; k2 < 32; k2++) {
        const ull zz = pack2(vin[k2], vin[k2]);
        const ulonglong2* wr = reinterpret_cast<const ulonglong2*>(Wsm + k2 * 32);
        #pragma unroll
        for (int j = 0; j < 8; j++) {
            const ulonglong2 w = wr[j];
            acc[2*j]     = ffma2(zz, w.x, acc[2*j]);
            acc[2*j + 1] = ffma2(zz, w.y, acc[2*j + 1]);
        }
    }
}

// ---------------------------------------------------------------------------
// Kernel 3: merged 4-expert forward, packed f32x2, PHASED weight staging.
// One 32KB buffer restaged 5x (Wq+Wk -> Wv -> Wo -> W1 -> W2) so total smem
// ~109KB -> 2 blocks/SM (4 warps/SMSP, whole grid in one wave).
// Math identical to the 117.5us kernel.
// ---------------------------------------------------------------------------
#define KV_STRIDE 36
#define OFF_LN1G 8192
#define OFF_LN1B 8320
#define OFF_LN2G 8448
#define OFF_LN2B 8576
#define OFF_B1   8704
#define OFF_B2   8960
#define OFF_SSW  9088
#define OFF_SSB  9120
#define OFF_KC   9152
#define OFF_VC   9280
#define OFF_INTS 9408
#define OFF_K    9440
#define OFF_V    (OFF_K + SB * KV_STRIDE)
#define SMEM_FLOATS (OFF_V + SB * KV_STRIDE)

__global__ void __launch_bounds__(256, 2) expert_kernel(
    const float* __restrict__ startW, const float* __restrict__ startb,
    const float* __restrict__ Wq, const float* __restrict__ Wk,
    const float* __restrict__ Wv, const float* __restrict__ Wo,
    const float* __restrict__ ln1g, const float* __restrict__ ln1b,
    const float* __restrict__ ln2g, const float* __restrict__ ln2b,
    const float* __restrict__ W1, const float* __restrict__ b1,
    const float* __restrict__ W2, const float* __restrict__ b2,
    float* __restrict__ out)
{
    extern __shared__ float sm[];
    float* sKc = sm + OFF_KC;
    float* sVc = sm + OFF_VC;
    float* Ksm = sm + OFF_K;
    float* Vsm = sm + OFF_V;
    int*   sI  = reinterpret_cast<int*>(sm + OFF_INTS);

    const int t = threadIdx.x;
    const int n = blockIdx.x, b = blockIdx.y;

    // ================= Phase A: stage Wq+Wk (32KB) + scalars ================
    {
        const float4* gq = reinterpret_cast<const float4*>(Wq);
        const float4* gk = reinterpret_cast<const float4*>(Wk);
        #pragma unroll
        for (int i = t; i < 1024; i += 256) {
            const int e_ = i >> 8, idx = i & 255;
            float4* dst = reinterpret_cast<float4*>(sm + e_ * 2048);
            dst[idx]       = gq[i];   // Wq_e at buf + e*2048
            dst[256 + idx] = gk[i];   // Wk_e at buf + e*2048 + 1024
        }
        if (t < 128) {
            sm[OFF_LN1G + t] = ln1g[t];
            sm[OFF_LN1B + t] = ln1b[t];
            sm[OFF_LN2G + t] = ln2g[t];
            sm[OFF_LN2B + t] = ln2b[t];
            sm[OFF_B2 + t]   = b2[t];
        }
        sm[OFF_B1 + t] = b1[t];
        if (t < 32) {
            sm[OFF_SSW + t] = startW[t];
            sm[OFF_SSB + t] = startb[t];
        }
        if (t < 4) {
            sI[t]     = g_off[b * EB + t];
            sI[4 + t] = g_ecnt[b * EB + t];
        }
    }
    __syncthreads();

    const float* ssW = sm + OFF_SSW;
    const float* ssb = sm + OFF_SSB;

    // ---- this thread's query ----
    const int e = (t >= sI[1]) + (t >= sI[2]) + (t >= sI[3]);
    const int s = g_glist[b * SB + t];
    const float xval = g_xns[(b * SB + s) * NB + n];

    const float* l1g_ = sm + OFF_LN1G + e * 32;
    const float* l1b_ = sm + OFF_LN1B + e * 32;
    const float* l2g_ = sm + OFF_LN2G + e * 32;
    const float* l2b_ = sm + OFF_LN2B + e * 32;
    const float* b1_  = sm + OFF_B1 + e * 64;
    const float* b2_  = sm + OFF_B2 + e * 32;

    // ---- z = LN1(xval*startW + startb) ----
    float z[32];
    {
        float mean = 0.f;
        #pragma unroll
        for (int d = 0; d < 32; d++) { z[d] = fmaf(xval, ssW[d], ssb[d]); mean += z[d]; }
        mean *= (1.f / 32.f);
        float var = 0.f;
        #pragma unroll
        for (int d = 0; d < 32; d++) { float dd = z[d] - mean; var = fmaf(dd, dd, var); }
        var *= (1.f / 32.f);
        float r = rsqrtf(var + 1e-5f);
        #pragma unroll
        for (int d = 0; d < 32; d++)
            z[d] = fmaf((z[d] - mean) * r, l1g_[d], l1b_[d]);
    }

    // ---- q (packed, scale folded in) from Wq; K row from Wk ----
    const float att_scale = 0.3535533905932738f; // 1/sqrt(8)
    ull q2[16];
    {
        #pragma unroll
        for (int i = 0; i < 16; i++) q2[i] = 0ull;
        matvec32p(sm + e * 2048, z, q2);
        const ull sc2 = pack2(att_scale, att_scale);
        #pragma unroll
        for (int i = 0; i < 16; i++) q2[i] = fmul2(q2[i], sc2);
    }
    {
        ull acc[16];
        #pragma unroll
        for (int i = 0; i < 16; i++) acc[i] = 0ull;
        matvec32p(sm + e * 2048 + 1024, z, acc);
        ulonglong2* kw = reinterpret_cast<ulonglong2*>(Ksm + t * KV_STRIDE);
        #pragma unroll
        for (int j = 0; j < 8; j++) {
            ulonglong2 v; v.x = acc[2*j]; v.y = acc[2*j+1];
            kw[j] = v;
        }
    }
    // ---- per-expert constant key (h_const = start_b) from Wk ----
    if (t < 128) {
        const int ce = t >> 5;
        const int d  = t & 31;
        float m = 0.f;
        #pragma unroll
        for (int dd = 0; dd < 32; dd++) m += ssb[dd];
        m *= (1.f / 32.f);
        float var = 0.f;
        #pragma unroll
        for (int dd = 0; dd < 32; dd++) { float df = ssb[dd] - m; var = fmaf(df, df, var); }
        var *= (1.f / 32.f);
        const float r = rsqrtf(var + 1e-5f);
        const float* cl1g = sm + OFF_LN1G + ce * 32;
        const float* cl1b = sm + OFF_LN1B + ce * 32;
        const float* wk_  = sm + ce * 2048 + 1024;
        float kc = 0.f;
        #pragma unroll
        for (int k2 = 0; k2 < 32; k2++) {
            float zc = fmaf((ssb[k2] - m) * r, cl1g[k2], cl1b[k2]);
            kc = fmaf(zc, wk_[k2 * 32 + d], kc);
        }
        sKc[ce * 32 + d] = kc;
    }
    __syncthreads();   // done with Wq/Wk

    // ================= Phase B: stage Wv (16KB) ============================
    {
        const float4* gv = reinterpret_cast<const float4*>(Wv);
        #pragma unroll
        for (int i = t; i < 1024; i += 256) {
            const int e_ = i >> 8, idx = i & 255;
            reinterpret_cast<float4*>(sm + e_ * 1024)[idx] = gv[i];  // Wv_e at buf + e*1024
        }
    }
    __syncthreads();

    // ---- V row from Wv ----
    {
        ull acc[16];
        #pragma unroll
        for (int i = 0; i < 16; i++) acc[i] = 0ull;
        matvec32p(sm + e * 1024, z, acc);
        ulonglong2* vw = reinterpret_cast<ulonglong2*>(Vsm + t * KV_STRIDE);
        #pragma unroll
        for (int j = 0; j < 8; j++) {
            ulonglong2 v; v.x = acc[2*j]; v.y = acc[2*j+1];
            vw[j] = v;
        }
    }
    // ---- per-expert constant value from Wv ----
    if (t < 128) {
        const int ce = t >> 5;
        const int d  = t & 31;
        float m = 0.f;
        #pragma unroll
        for (int dd = 0; dd < 32; dd++) m += ssb[dd];
        m *= (1.f / 32.f);
        float var = 0.f;
        #pragma unroll
        for (int dd = 0; dd < 32; dd++) { float df = ssb[dd] - m; var = fmaf(df, df, var); }
        var *= (1.f / 32.f);
        const float r = rsqrtf(var + 1e-5f);
        const float* cl1g = sm + OFF_LN1G + ce * 32;
        const float* cl1b = sm + OFF_LN1B + ce * 32;
        const float* wv_  = sm + ce * 1024;
        float vc = 0.f;
        #pragma unroll
        for (int k2 = 0; k2 < 32; k2++) {
            float zc = fmaf((ssb[k2] - m) * r, cl1g[k2], cl1b[k2]);
            vc = fmaf(zc, wv_[k2 * 32 + d], vc);
        }
        sVc[ce * 32 + d] = vc;
    }
    __syncthreads();   // K, V, kc, vc all visible; done with Wv

    // ================= Phase C: stage Wo, then attention ===================
    {
        const float4* go = reinterpret_cast<const float4*>(Wo);
        #pragma unroll
        for (int i = t; i < 1024; i += 256) {
            const int e_ = i >> 8, idx = i & 255;
            reinterpret_cast<float4*>(sm + e_ * 1024)[idx] = go[i];  // Wo_e at buf + e*1024
        }
    }
    // (no sync needed before attention: attention touches only Ksm/Vsm/sKc/sVc)

    const int koff = sI[e];
    const int kend = koff + sI[4 + e];

    ull o2[16];
    #pragma unroll
    for (int i = 0; i < 16; i++) o2[i] = 0ull;
    float lsum[4] = {0.f, 0.f, 0.f, 0.f};

    #pragma unroll 2
    for (int key = koff; key < kend; key++) {
        const ulonglong2* kr = reinterpret_cast<const ulonglong2*>(Ksm + key * KV_STRIDE);
        const ulonglong2* vr = reinterpret_cast<const ulonglong2*>(Vsm + key * KV_STRIDE);
        #pragma unroll
        for (int hh = 0; hh < 4; hh++) {
            const ulonglong2 k01 = kr[2*hh], k23 = kr[2*hh + 1];
            ull lg2 = fmul2(q2[4*hh], k01.x);
            lg2 = ffma2(q2[4*hh + 1], k01.y, lg2);
            lg2 = ffma2(q2[4*hh + 2], k23.x, lg2);
            lg2 = ffma2(q2[4*hh + 3], k23.y, lg2);
            float lo, hi;
            unpack2(lg2, lo, hi);
            const float p = __expf(fminf(lo + hi, 80.f));
            lsum[hh] += p;
            const ull pp = pack2(p, p);
            const ulonglong2 v01 = vr[2*hh], v23 = vr[2*hh + 1];
            o2[4*hh]     = ffma2(pp, v01.x, o2[4*hh]);
            o2[4*hh + 1] = ffma2(pp, v01.y, o2[4*hh + 1]);
            o2[4*hh + 2] = ffma2(pp, v23.x, o2[4*hh + 2]);
            o2[4*hh + 3] = ffma2(pp, v23.y, o2[4*hh + 3]);
        }
    }
    {
        const float w = (float)(SB - sI[4 + e]);
        const ulonglong2* kr = reinterpret_cast<const ulonglong2*>(sKc + e * 32);
        const ulonglong2* vr = reinterpret_cast<const ulonglong2*>(sVc + e * 32);
        #pragma unroll
        for (int hh = 0; hh < 4; hh++) {
            const ulonglong2 k01 = kr[2*hh], k23 = kr[2*hh + 1];
            ull lg2 = fmul2(q2[4*hh], k01.x);
            lg2 = ffma2(q2[4*hh + 1], k01.y, lg2);
            lg2 = ffma2(q2[4*hh + 2], k23.x, lg2);
            lg2 = ffma2(q2[4*hh + 3], k23.y, lg2);
            float lo, hi;
            unpack2(lg2, lo, hi);
            const float p = w * __expf(fminf(lo + hi, 80.f));
            lsum[hh] += p;
            const ull pp = pack2(p, p);
            const ulonglong2 v01 = vr[2*hh], v23 = vr[2*hh + 1];
            o2[4*hh]     = ffma2(pp, v01.x, o2[4*hh]);
            o2[4*hh + 1] = ffma2(pp, v01.y, o2[4*hh + 1]);
            o2[4*hh + 2] = ffma2(pp, v23.x, o2[4*hh + 2]);
            o2[4*hh + 3] = ffma2(pp, v23.y, o2[4*hh + 3]);
        }
    }

    // normalize o
    float o[32];
    #pragma unroll
    for (int hh = 0; hh < 4; hh++) {
        const float inv = 1.0f / lsum[hh];
        #pragma unroll
        for (int j = 0; j < 4; j++) {
            float a, c;
            unpack2(o2[4*hh + j], a, c);
            o[8*hh + 2*j]     = a * inv;
            o[8*hh + 2*j + 1] = c * inv;
        }
    }
    __syncthreads();   // Wo staged by all threads; attention done

    // ---- h2 = h + o @ Wo (packed acc seeded with residual) ----
    float h2[32];
    {
        ull acc[16];
        #pragma unroll
        for (int j = 0; j < 16; j++) {
            const float r0 = fmaf(xval, ssW[2*j],     ssb[2*j]);
            const float r1 = fmaf(xval, ssW[2*j + 1], ssb[2*j + 1]);
            acc[j] = pack2(r0, r1);
        }
        matvec32p(sm + e * 1024, o, acc);
        #pragma unroll
        for (int j = 0; j < 16; j++) unpack2(acc[j], h2[2*j], h2[2*j + 1]);
    }
    __syncthreads();   // done with Wo

    // ================= Phase D: stage W1 (32KB) ============================
    {
        const float4* g1 = reinterpret_cast<const float4*>(W1);
        #pragma unroll
        for (int i = t; i < 2048; i += 256) {
            const int e_ = i >> 9, idx = i & 511;
            reinterpret_cast<float4*>(sm + e_ * 2048)[idx] = g1[i];  // W1_e at buf + e*2048
        }
    }
    __syncthreads();

    // ---- z2 = LN2(h2) ----
    float z2[32];
    {
        float mean = 0.f;
        #pragma unroll
        for (int d = 0; d < 32; d++) mean += h2[d];
        mean *= (1.f / 32.f);
        float var = 0.f;
        #pragma unroll
        for (int d = 0; d < 32; d++) { float dd = h2[d] - mean; var = fmaf(dd, dd, var); }
        var *= (1.f / 32.f);
        float r = rsqrtf(var + 1e-5f);
        #pragma unroll
        for (int d = 0; d < 32; d++)
            z2[d] = fmaf((h2[d] - mean) * r, l2g_[d], l2b_[d]);
    }

    // ---- fh = relu(z2 @ W1 + b1), all 64 f-dims (two 32-wide halves) ----
    float fh[64];
    {
        const float* sW1 = sm + e * 2048;
        #pragma unroll
        for (int half = 0; half < 2; half++) {
            ull fh2[16];
            #pragma unroll
            for (int j = 0; j < 16; j++)
                fh2[j] = pack2(b1_[half*32 + 2*j], b1_[half*32 + 2*j + 1]);
            #pragma unroll
            for (int k2 = 0; k2 < 32; k2++) {
                const ull zz = pack2(z2[k2], z2[k2]);
                const ulonglong2* wr =
                    reinterpret_cast<const ulonglong2*>(sW1 + k2 * 64 + half * 32);
                #pragma unroll
                for (int j = 0; j < 16; j++) {
                    const ulonglong2 w = wr[j >> 1];
                    fh2[j] = ffma2(zz, (j & 1) ? w.y : w.x, fh2[j]);
                }
            }
            #pragma unroll
            for (int j = 0; j < 16; j++) {
                float a, c;
                unpack2(fh2[j], a, c);
                fh[half*32 + 2*j]     = fmaxf(a, 0.f);
                fh[half*32 + 2*j + 1] = fmaxf(c, 0.f);
            }
        }
    }
    __syncthreads();   // done with W1

    // ================= Phase E: stage W2 (32KB) ============================
    {
        const float4* g2 = reinterpret_cast<const float4*>(W2);
        #pragma unroll
        for (int i = t; i < 2048; i += 256) {
            const int e_ = i >> 9, idx = i & 511;
            reinterpret_cast<float4*>(sm + e_ * 2048)[idx] = g2[i];  // W2_e at buf + e*2048
        }
    }
    __syncthreads();

    // ---- h3 = h2 + b2 + fh @ W2 ----
    ull h32[16];
    #pragma unroll
    for (int j = 0; j < 16; j++)
        h32[j] = pack2(h2[2*j] + b2_[2*j], h2[2*j + 1] + b2_[2*j + 1]);
    {
        const float* sW2 = sm + e * 2048;
        #pragma unroll
        for (int half = 0; half < 2; half++) {
            #pragma unroll
            for (int j = 0; j < 32; j++) {
                const ull fj = pack2(fh[half*32 + j], fh[half*32 + j]);
                const ulonglong2* wr =
                    reinterpret_cast<const ulonglong2*>(sW2 + (half * 32 + j) * 32);
                #pragma unroll
                for (int d = 0; d < 16; d++) {
                    const ulonglong2 w = wr[d >> 1];
                    h32[d] = ffma2(fj, (d & 1) ? w.y : w.x, h32[d]);
                }
            }
        }
    }

    // ---- write: each (b,s) handled by exactly one thread per n ----
    {
        const int bs = b * SB + s;
        ulonglong2* op = reinterpret_cast<ulonglong2*>(out + ((bs * NB) + n) * DB);
        #pragma unroll
        for (int j = 0; j < 8; j++) {
            ulonglong2 v; v.x = h32[2*j]; v.y = h32[2*j + 1];
            op[j] = v;
        }
    }
}

// ---------------------------------------------------------------------------
extern "C" void kernel_launch(void* const* d_in, const int* in_sizes, int n_in,
                              void* d_out, int out_size)
{
    const float* x      = (const float*)d_in[0];
    const float* orig   = (const float*)d_in[1];
    const float* startW = (const float*)d_in[2];
    const float* startb = (const float*)d_in[3];
    const float* Wq     = (const float*)d_in[4];
    const float* Wk     = (const float*)d_in[5];
    const float* Wv     = (const float*)d_in[6];
    const float* Wo     = (const float*)d_in[7];
    const float* l1g    = (const float*)d_in[8];
    const float* l1b    = (const float*)d_in[9];
    const float* l2g    = (const float*)d_in[10];
    const float* l2b    = (const float*)d_in[11];
    const float* W1     = (const float*)d_in[12];
    const float* b1     = (const float*)d_in[13];
    const float* W2     = (const float*)d_in[14];
    const float* b2     = (const float*)d_in[15];
    float* out = (float*)d_out;

    preprocess_kernel<<<dim3(NB, BB), 256>>>(x);
    assign_kernel<<<1, 256>>>(orig);

    const int smem_bytes = SMEM_FLOATS * (int)sizeof(float);
    cudaFuncSetAttribute(expert_kernel,
                         cudaFuncAttributeMaxDynamicSharedMemorySize, smem_bytes);
    expert_kernel<<<dim3(NB, BB), 256, smem_bytes>>>(
        startW, startb, Wq, Wk, Wv, Wo,
        l1g, l1b, l2g, l2b, W1, b1, W2, b2, out);
}